// round 1
// baseline (speedup 1.0000x reference)
#include <cuda_runtime.h>
#include <cstdint>

// Problem constants (fixed shapes)
#define BB 32
#define TT 8192
#define II 16
#define HH 128
#define GG 512      // 4*H
#define OO 3
#define PP 1024
#define KTOT 148    // 128 (h) + 16 (x) + 1 (bias) padded to 148 = 37 float4
#define KREG_F4 18  // k = 0..71 in registers
#define KSMEM_F4 19 // k = 72..147 in shared
#define NTHR 512

__device__ __forceinline__ float fsig(float x) {
    // 1/(1+exp(-x)); saturates correctly for |x| large (exp->inf -> 0)
    return __fdividef(1.0f, 1.0f + __expf(-x));
}
__device__ __forceinline__ float ftanh(float x) {
    return 2.0f * __fdividef(1.0f, 1.0f + __expf(-2.0f * x)) - 1.0f;
}

// Fetch combined weight element for gate-row g, position k.
__device__ __forceinline__ float wfetch(const float* __restrict__ Whh,
                                        const float* __restrict__ Wih,
                                        const float* __restrict__ bih,
                                        const float* __restrict__ bhh,
                                        int g, int k) {
    if (k < 128) return Whh[g * 128 + k];
    if (k < 144) return Wih[g * 16 + (k - 128)];
    if (k == 144) return bih[g] + bhh[g];
    return 0.0f;
}

__global__ void __launch_bounds__(NTHR, 1)
lstm_seg_kernel(const float* __restrict__ x,
                const float* __restrict__ W_ih,
                const float* __restrict__ W_hh,
                const float* __restrict__ b_ih,
                const float* __restrict__ b_hh,
                const float* __restrict__ W_fc,
                const float* __restrict__ b_fc,
                float* __restrict__ out) {
    extern __shared__ float sm[];
    // Shared layout (floats):
    float* w4s_f  = sm;                              // KSMEM_F4*512*4 = 38912
    float* hx     = w4s_f + KSMEM_F4 * GG * 4;       // 148  (16B aligned)
    float* gact   = hx + KTOT;                        // 512
    float* wfc_s  = gact + GG;                        // 384
    float* fcpart = wfc_s + 384;                      // 16 (12 used)
    float* sums   = fcpart + 16;                      // 3072
    float* cntb   = sums + PP * OO;                   // 1024
    // total = 38912+148+512+384+16+3072+1024 = 44068 floats

    const int tid = threadIdx.x;
    const int b   = blockIdx.x;
    const int g   = tid;
    float4* w4 = reinterpret_cast<float4*>(w4s_f);

    // ---- Prologue ----
    // Zero segment accumulators
    for (int i = tid; i < PP * OO; i += NTHR) sums[i] = 0.0f;
    for (int i = tid; i < PP; i += NTHR) cntb[i] = 0.0f;
    // W_fc into shared (layout [o*128 + j], identical to input)
    if (tid < OO * HH) wfc_s[tid] = W_fc[tid];
    // hx init: h=0, x = x[b][0][:], bias lane, pad
    if (tid < KTOT) {
        float v = 0.0f;
        if (tid < 128)            v = 0.0f;
        else if (tid < 144)       v = x[((size_t)b * TT + 0) * II + (tid - 128)];
        else if (tid == 144)      v = 1.0f;
        hx[tid] = v;
    }
    // Register-resident weights: k = 0..71
    float4 wreg[KREG_F4];
#pragma unroll
    for (int j = 0; j < KREG_F4; j++) {
        int k = j * 4;
        wreg[j].x = wfetch(W_hh, W_ih, b_ih, b_hh, g, k + 0);
        wreg[j].y = wfetch(W_hh, W_ih, b_ih, b_hh, g, k + 1);
        wreg[j].z = wfetch(W_hh, W_ih, b_ih, b_hh, g, k + 2);
        wreg[j].w = wfetch(W_hh, W_ih, b_ih, b_hh, g, k + 3);
    }
    // Shared-resident weights: k = 72..147, layout w4[j*512 + g] (conflict-free LDS.128)
    for (int j = 0; j < KSMEM_F4; j++) {
        int k = (KREG_F4 + j) * 4;
        float4 w;
        w.x = wfetch(W_hh, W_ih, b_ih, b_hh, g, k + 0);
        w.y = wfetch(W_hh, W_ih, b_ih, b_hh, g, k + 1);
        w.z = wfetch(W_hh, W_ih, b_ih, b_hh, g, k + 2);
        w.w = wfetch(W_hh, W_ih, b_ih, b_hh, g, k + 3);
        w4[j * GG + g] = w;
    }
    float bfc0 = 0.f, bfc1 = 0.f, bfc2 = 0.f;
    if (tid == 511) { bfc0 = b_fc[0]; bfc1 = b_fc[1]; bfc2 = b_fc[2]; }

    float c_state = 0.0f;   // cell state, live in threads 0..127
    int id_pending = 0;

    __syncthreads();

    // ---- Time loop ----
    for (int t = 0; t < TT; t++) {
        // ===== Phase A: fused matvec (gates) for step t; overlapped extras =====
        float xnext = 0.0f;
        if (tid >= 128 && tid < 144) {
            int tn = t + 1;
            if (tn < TT) xnext = x[((size_t)b * TT + tn) * II + (tid - 128)];
        }
        if (tid == 511) {
            if (t > 0) {
                // finalize FC for step t-1 and accumulate into segment sums
                float s0 = fcpart[0] + fcpart[3] + fcpart[6] + fcpart[9]  + bfc0;
                float s1 = fcpart[1] + fcpart[4] + fcpart[7] + fcpart[10] + bfc1;
                float s2 = fcpart[2] + fcpart[5] + fcpart[8] + fcpart[11] + bfc2;
                unsigned pid = (unsigned)id_pending;
                if (pid < PP) {
                    sums[pid * 3 + 0] += s0;
                    sums[pid * 3 + 1] += s1;
                    sums[pid * 3 + 2] += s2;
                    cntb[pid] += 1.0f;
                }
            }
            id_pending = (int)hx[128 + 2];   // photo id of current step t
        }

        const float4* hx4 = reinterpret_cast<const float4*>(hx);
        float acc0 = 0.0f, acc1 = 0.0f;
#pragma unroll
        for (int j = 0; j < KREG_F4; j++) {
            float4 v = hx4[j];
            acc0 = fmaf(wreg[j].x, v.x, acc0);
            acc1 = fmaf(wreg[j].y, v.y, acc1);
            acc0 = fmaf(wreg[j].z, v.z, acc0);
            acc1 = fmaf(wreg[j].w, v.w, acc1);
        }
#pragma unroll
        for (int j = 0; j < KSMEM_F4; j++) {
            float4 v = hx4[KREG_F4 + j];
            float4 w = w4[j * GG + g];
            acc0 = fmaf(w.x, v.x, acc0);
            acc1 = fmaf(w.y, v.y, acc1);
            acc0 = fmaf(w.z, v.z, acc0);
            acc1 = fmaf(w.w, v.w, acc1);
        }
        float pre = acc0 + acc1;
        float act = (g >= 256 && g < 384) ? ftanh(pre) : fsig(pre);
        gact[g] = act;
        __syncthreads();

        // ===== Phase B: state update + FC partials; x staging =====
        if (tid < 128) {
            float iv = gact[tid];
            float fv = gact[128 + tid];
            float gv = gact[256 + tid];
            float ov = gact[384 + tid];
            c_state = fmaf(fv, c_state, iv * gv);
            float hval = ov * ftanh(c_state);
            hx[tid] = hval;
            // FC partials for this step
            float p0 = hval * wfc_s[tid];
            float p1 = hval * wfc_s[128 + tid];
            float p2 = hval * wfc_s[256 + tid];
#pragma unroll
            for (int off = 16; off > 0; off >>= 1) {
                p0 += __shfl_down_sync(0xffffffffu, p0, off);
                p1 += __shfl_down_sync(0xffffffffu, p1, off);
                p2 += __shfl_down_sync(0xffffffffu, p2, off);
            }
            if ((tid & 31) == 0) {
                int w = tid >> 5;
                fcpart[w * 3 + 0] = p0;
                fcpart[w * 3 + 1] = p1;
                fcpart[w * 3 + 2] = p2;
            }
        } else if (tid < 144) {
            hx[tid] = xnext;   // stage x for step t+1
        }
        __syncthreads();
    }

    // ---- finalize FC for last step ----
    if (tid == 511) {
        float s0 = fcpart[0] + fcpart[3] + fcpart[6] + fcpart[9]  + bfc0;
        float s1 = fcpart[1] + fcpart[4] + fcpart[7] + fcpart[10] + bfc1;
        float s2 = fcpart[2] + fcpart[5] + fcpart[8] + fcpart[11] + bfc2;
        unsigned pid = (unsigned)id_pending;
        if (pid < PP) {
            sums[pid * 3 + 0] += s0;
            sums[pid * 3 + 1] += s1;
            sums[pid * 3 + 2] += s2;
            cntb[pid] += 1.0f;
        }
    }
    __syncthreads();

    // ---- Epilogue: divide by counts, write out [b][p][o] ----
    for (int idx = tid; idx < PP * OO; idx += NTHR) {
        int p = idx / 3;
        float cc = cntb[p];
        if (cc == 0.0f) cc = 1.0f;
        out[(size_t)b * PP * OO + idx] = sums[idx] / cc;
    }
}

extern "C" void kernel_launch(void* const* d_in, const int* in_sizes, int n_in,
                              void* d_out, int out_size) {
    const float* x    = (const float*)d_in[0];
    const float* W_ih = (const float*)d_in[1];
    const float* W_hh = (const float*)d_in[2];
    const float* b_ih = (const float*)d_in[3];
    const float* b_hh = (const float*)d_in[4];
    const float* W_fc = (const float*)d_in[5];
    const float* b_fc = (const float*)d_in[6];
    float* out = (float*)d_out;

    const int smem_bytes = 44068 * 4;   // 176272 B
    static bool attr_set = false;
    if (!attr_set) {
        cudaFuncSetAttribute(lstm_seg_kernel,
                             cudaFuncAttributeMaxDynamicSharedMemorySize,
                             smem_bytes);
        attr_set = true;
    }
    lstm_seg_kernel<<<BB, NTHR, smem_bytes>>>(x, W_ih, W_hh, b_ih, b_hh,
                                              W_fc, b_fc, out);
}

// round 2
// speedup vs baseline: 2.1287x; 2.1287x over previous
#include <cuda_runtime.h>
#include <cstdint>

// Shapes (fixed)
#define BB 32
#define TT 8192
#define II 16
#define HH 128
#define OO 3
#define PP 1024
#define CL 4            // cluster size (CTAs per batch)
#define NTHR 576        // 512 matvec + 32 FC + 32 comm/x
#define HXF 160         // floats per hx ring buffer (144 used: 128 h + 16 x)
#define K_PER 36        // k-positions per matvec thread (4 threads x 36 = 144)

// Shared layout (float offsets unless noted)
#define OFF_HXB 0                 // 3 * 160 = 480 floats
#define OFF_MBAR_BYTES 1920       // 3 x 8B mbarriers at byte 1920..1943
#define OFF_SUMS 488              // 1024*3 floats
#define OFF_CNT 3560              // 1024 floats
#define SMEM_FLOATS 4584
#define TXB 576                   // expected tx bytes per step per CTA: 128*4 (h) + 16*4 (x)

__device__ __forceinline__ uint32_t smem_u32(const void* p) {
    uint32_t a;
    asm("{ .reg .u64 t; cvta.to.shared.u64 t, %1; cvt.u32.u64 %0, t; }"
        : "=r"(a) : "l"(p));
    return a;
}
__device__ __forceinline__ uint32_t mapa_u32(uint32_t a, uint32_t r) {
    uint32_t d;
    asm("mapa.shared::cluster.u32 %0, %1, %2;" : "=r"(d) : "r"(a), "r"(r));
    return d;
}
__device__ __forceinline__ void st_async_f32(uint32_t addr, float v, uint32_t mbar) {
    asm volatile("st.async.shared::cluster.mbarrier::complete_tx::bytes.b32 [%0], %1, [%2];"
                 :: "r"(addr), "r"(__float_as_uint(v)), "r"(mbar) : "memory");
}
__device__ __forceinline__ void mbar_init(uint32_t mbar, uint32_t cnt) {
    asm volatile("mbarrier.init.shared.b64 [%0], %1;" :: "r"(mbar), "r"(cnt) : "memory");
}
__device__ __forceinline__ void mbar_expect_tx(uint32_t mbar, uint32_t tx) {
    asm volatile("mbarrier.arrive.expect_tx.shared.b64 _, [%0], %1;"
                 :: "r"(mbar), "r"(tx) : "memory");
}
__device__ __forceinline__ void mbar_wait(uint32_t mbar, unsigned parity) {
    asm volatile(
        "{\n\t.reg .pred P;\n"
        "W%=:\n\t"
        "mbarrier.try_wait.parity.acquire.cta.shared::cta.b64 P, [%0], %1, 10000000;\n\t"
        "@!P bra W%=;\n\t"
        "}" :: "r"(mbar), "r"(parity) : "memory");
}
__device__ __forceinline__ float fsig(float v)  { return __fdividef(1.0f, 1.0f + __expf(-v)); }
__device__ __forceinline__ float ftanh(float v) { return 2.0f * __fdividef(1.0f, 1.0f + __expf(-2.0f * v)) - 1.0f; }

__global__ void __launch_bounds__(NTHR, 1) __cluster_dims__(CL, 1, 1)
lstm_cluster_kernel(const float* __restrict__ x,
                    const float* __restrict__ W_ih,
                    const float* __restrict__ W_hh,
                    const float* __restrict__ b_ih,
                    const float* __restrict__ b_hh,
                    const float* __restrict__ W_fc,
                    const float* __restrict__ b_fc,
                    float* __restrict__ out) {
    __shared__ __align__(16) float smf[SMEM_FLOATS];
    const int tid  = threadIdx.x;
    const int warp = tid >> 5;
    const int lane = tid & 31;
    uint32_t R;
    asm("mov.u32 %0, %%cluster_ctarank;" : "=r"(R));
    const int b = blockIdx.x >> 2;

    const uint32_t sbase = smem_u32(smf);
    uint32_t pbase[CL];
#pragma unroll
    for (int c = 0; c < CL; c++) pbase[c] = mapa_u32(sbase, (uint32_t)c);
    const uint32_t lbase = pbase[0] + (sbase - pbase[0]); // == sbase; local cta-space ok for self

    // ---- Prologue: zero accumulators, init barriers, fill ring buffer 0 ----
    for (int i = tid; i < PP * OO; i += NTHR) smf[OFF_SUMS + i] = 0.0f;
    for (int i = tid; i < PP; i += NTHR)      smf[OFF_CNT + i]  = 0.0f;
    if (tid == 0) {
#pragma unroll
        for (int s = 0; s < 3; s++) mbar_init(sbase + OFF_MBAR_BYTES + 8 * s, 1);
    }
    if (tid < HH) smf[OFF_HXB + tid] = 0.0f;                                  // h(-1) = 0
    if (tid < II) smf[OFF_HXB + HH + tid] = x[((size_t)b * TT) * II + tid];   // x(0)
    __syncthreads();
    asm volatile("barrier.cluster.arrive.aligned;" ::: "memory");
    asm volatile("barrier.cluster.wait.aligned;" ::: "memory");

    // ---- Role prologues ----
    // Matvec (tid < 512): warp holds 8 gate-rows; lane = (row_in_warp)*4 + j.
    // row_cta = hl*4 + gate, hl = 2*warp + (lane>>4), gate = (lane>>2)&3, j = lane&3.
    float4 wv[9];
    float  bias = 0.0f, c_state = 0.0f;
    int    j = 0, hg = 0;
    bool   is_h = false;
    if (tid < 512) {
        j = lane & 3;
        const int gate = (lane >> 2) & 3;
        const int hl   = 2 * warp + (lane >> 4);
        hg = 32 * (int)R + hl;
        const int row = gate * HH + hg;
        if (j < 3) {
            const float4* wp = (const float4*)(W_hh + (size_t)row * HH + j * K_PER);
#pragma unroll
            for (int m = 0; m < 9; m++) wv[m] = wp[m];
        } else {
            const float4* wp = (const float4*)(W_hh + (size_t)row * HH + 108);
#pragma unroll
            for (int m = 0; m < 5; m++) wv[m] = wp[m];
            const float4* wq = (const float4*)(W_ih + (size_t)row * II);
#pragma unroll
            for (int m = 0; m < 4; m++) wv[5 + m] = wq[m];
        }
        if (j == 0) bias = b_ih[row] + b_hh[row];
        is_h = ((lane & 15) == 0);   // gate==0 && j==0 -> owns h[hg], c[hg]
    }
    // FC warp (warp 16): per-lane FC weights for h index 32R+lane
    float wfc0 = 0.f, wfc1 = 0.f, wfc2 = 0.f, bfc0 = 0.f, bfc1 = 0.f, bfc2 = 0.f;
    if (warp == 16) {
        const int hi = 32 * (int)R + lane;
        wfc0 = W_fc[hi]; wfc1 = W_fc[HH + hi]; wfc2 = W_fc[2 * HH + hi];
        if (R == 0 && lane == 0) { bfc0 = b_fc[0]; bfc1 = b_fc[1]; bfc2 = b_fc[2]; }
    }
    // Comm warp (warp 17): x prefetch register holds x(t+1) at top of step t
    float xr = 0.0f;
    if (warp == 17 && lane < II) xr = x[((size_t)b * TT + 1) * II + lane];

    int pid = 0;
    unsigned par0 = 0, par1 = 0, par2 = 0;
    int cur = 0;

    // ---- Time loop ----
    for (int t = 0; t < TT; t++) {
        int nxt = cur + 1; if (nxt == 3) nxt = 0;
        if (t > 0) {
            if (tid == 0) {
                unsigned parity = (cur == 0) ? par0 : ((cur == 1) ? par1 : par2);
                mbar_wait(sbase + OFF_MBAR_BYTES + 8 * cur, parity);
            }
            if (cur == 0) par0 ^= 1; else if (cur == 1) par1 ^= 1; else par2 ^= 1;
        }
        __syncthreads();
        const float* hxc = smf + OFF_HXB + cur * HXF;

        if (tid < 512) {
            const float4* hp = (const float4*)(hxc + j * K_PER);
            float a0 = bias, a1 = 0.f, a2 = 0.f, a3 = 0.f;
#pragma unroll
            for (int m = 0; m < 9; m++) {
                float4 h4 = hp[m];
                a0 = fmaf(wv[m].x, h4.x, a0);
                a1 = fmaf(wv[m].y, h4.y, a1);
                a2 = fmaf(wv[m].z, h4.z, a2);
                a3 = fmaf(wv[m].w, h4.w, a3);
            }
            float pre = (a0 + a1) + (a2 + a3);
            pre += __shfl_xor_sync(0xffffffffu, pre, 1);
            pre += __shfl_xor_sync(0xffffffffu, pre, 2);
            const int gate = (lane >> 2) & 3;
            float act = (gate == 2) ? ftanh(pre) : fsig(pre);
            const int b16 = lane & 16;
            float vi = __shfl_sync(0xffffffffu, act, b16);
            float vf = __shfl_sync(0xffffffffu, act, b16 + 4);
            float vg = __shfl_sync(0xffffffffu, act, b16 + 8);
            float vo = __shfl_sync(0xffffffffu, act, b16 + 12);
            if (is_h) {
                c_state = fmaf(vf, c_state, vi * vg);
                float hval = vo * ftanh(c_state);
                const uint32_t off   = (uint32_t)((OFF_HXB + nxt * HXF + hg) * 4);
                const uint32_t mboff = (uint32_t)(OFF_MBAR_BYTES + 8 * nxt);
#pragma unroll
                for (int c = 0; c < CL; c++)
                    st_async_f32(pbase[c] + off, hval, pbase[c] + mboff);
            }
        } else if (warp == 16) {
            // FC + segment accumulate for h(t-1) (in hxc), pid captured last step
            const int pid_next = (int)hxc[HH + 2];   // x(t)[2]
            if (t > 0) {
                float hv = hxc[32 * (int)R + lane];
                float p0 = hv * wfc0, p1 = hv * wfc1, p2 = hv * wfc2;
#pragma unroll
                for (int o = 16; o > 0; o >>= 1) {
                    p0 += __shfl_down_sync(0xffffffffu, p0, o);
                    p1 += __shfl_down_sync(0xffffffffu, p1, o);
                    p2 += __shfl_down_sync(0xffffffffu, p2, o);
                }
                if (lane == 0 && (unsigned)pid < PP) {
                    float* s = &smf[OFF_SUMS + pid * 3];
                    s[0] += p0 + bfc0; s[1] += p1 + bfc1; s[2] += p2 + bfc2;
                    if (R == 0) smf[OFF_CNT + pid] += 1.0f;
                }
            }
            pid = pid_next;
        } else {
            // Comm warp: stage x(t+1) into nxt buffer, prefetch x(t+2), post expect_tx
            if (lane < II) {
                const uint32_t off = (uint32_t)((OFF_HXB + nxt * HXF + HH + lane) * 4);
                st_async_f32(sbase + off, xr, sbase + OFF_MBAR_BYTES + 8 * nxt);
                xr = (t + 2 < TT) ? x[((size_t)b * TT + t + 2) * II + lane] : 0.0f;
            } else if (lane == 16) {
                mbar_expect_tx(sbase + OFF_MBAR_BYTES + 8 * nxt, TXB);
            }
        }
        cur = nxt;
    }

    // ---- Final FC round for h(TT-1) (in buffer cur == TT%3 == 2) ----
    if (tid == 0) mbar_wait(sbase + OFF_MBAR_BYTES + 8 * 2, par2);
    __syncthreads();
    if (warp == 16) {
        const float* hxc = smf + OFF_HXB + 2 * HXF;
        float hv = hxc[32 * (int)R + lane];
        float p0 = hv * wfc0, p1 = hv * wfc1, p2 = hv * wfc2;
#pragma unroll
        for (int o = 16; o > 0; o >>= 1) {
            p0 += __shfl_down_sync(0xffffffffu, p0, o);
            p1 += __shfl_down_sync(0xffffffffu, p1, o);
            p2 += __shfl_down_sync(0xffffffffu, p2, o);
        }
        if (lane == 0 && (unsigned)pid < PP) {
            float* s = &smf[OFF_SUMS + pid * 3];
            s[0] += p0 + bfc0; s[1] += p1 + bfc1; s[2] += p2 + bfc2;
            if (R == 0) smf[OFF_CNT + pid] += 1.0f;
        }
    }
    __syncthreads();
    asm volatile("barrier.cluster.arrive.aligned;" ::: "memory");
    asm volatile("barrier.cluster.wait.aligned;" ::: "memory");

    // ---- Epilogue: rank 0 gathers partial sums from peers via DSMEM, writes out ----
    if (R == 0) {
        for (int idx = tid; idx < PP * OO; idx += NTHR) {
            float s = smf[OFF_SUMS + idx];
#pragma unroll
            for (int c = 1; c < CL; c++) {
                const uint32_t ra = pbase[c] + (uint32_t)((OFF_SUMS + idx) * 4);
                float v;
                asm volatile("ld.shared::cluster.f32 %0, [%1];" : "=f"(v) : "r"(ra));
                s += v;
            }
            const int p = idx / 3;
            float cc = smf[OFF_CNT + p];
            if (cc == 0.0f) cc = 1.0f;
            out[(size_t)b * PP * OO + idx] = s / cc;
        }
    }
    asm volatile("barrier.cluster.arrive.aligned;" ::: "memory");
    asm volatile("barrier.cluster.wait.aligned;" ::: "memory");
    (void)lbase;
}

extern "C" void kernel_launch(void* const* d_in, const int* in_sizes, int n_in,
                              void* d_out, int out_size) {
    const float* x    = (const float*)d_in[0];
    const float* W_ih = (const float*)d_in[1];
    const float* W_hh = (const float*)d_in[2];
    const float* b_ih = (const float*)d_in[3];
    const float* b_hh = (const float*)d_in[4];
    const float* W_fc = (const float*)d_in[5];
    const float* b_fc = (const float*)d_in[6];
    float* out = (float*)d_out;
    lstm_cluster_kernel<<<BB * CL, NTHR>>>(x, W_ih, W_hh, b_ih, b_hh, W_fc, b_fc, out);
}